// round 13
// baseline (speedup 1.0000x reference)
#include <cuda_runtime.h>
#include <cuda_bf16.h>
#include <cstdint>

#define BB 64
#define SS 48
#define EE 512
#define HH 512
#define GG 2048
#define NCTA 128

// ---------------- persistent device scratch (no allocs allowed) ----------------
__device__ float g_gih0[2][SS][BB][GG];   // LN(x @ W_ih0^T), both dirs  (~50MB)
__device__ float g_u[2][BB][GG];          // per-step h @ W_hh^T (raw)
__device__ float g_h[2][BB][HH];
__device__ __nv_bfloat16 g_hbf[2][3][BB][HH];  // [dir][hi/mid/lo] bf16 3-way split of h
__device__ unsigned g_bar_d[2][32];       // per-direction barrier counters (padded)
__device__ unsigned g_bar_all = 0;        // full-grid join barrier
__device__ unsigned g_excnt = 0;

// fast activations (__expf err ~2^-22; verified in R12: no rel_err movement)
__device__ __forceinline__ float sigmoidf_(float x) {
    return __fdividef(1.0f, 1.0f + __expf(-x));
}
__device__ __forceinline__ float tanhf_(float x) {
    float xx = fminf(fmaxf(x, -15.f), 15.f);
    float e = __expf(2.f * xx);
    return __fdividef(e - 1.f, e + 1.f);
}

__device__ __forceinline__ uint32_t smem_u32(const void* p) {
    uint32_t a;
    asm("{ .reg .u64 t; cvta.to.shared.u64 t, %1; cvt.u32.u64 %0, t; }" : "=r"(a) : "l"(p));
    return a;
}

// ---------------- mma.sync helpers (baseline PTX; valid on sm_103) -------------
__device__ __forceinline__ void ldm_x4(uint32_t (&r)[4], uint32_t addr) {
    asm volatile("ldmatrix.sync.aligned.m8n8.x4.shared.b16 {%0,%1,%2,%3}, [%4];"
                 : "=r"(r[0]), "=r"(r[1]), "=r"(r[2]), "=r"(r[3]) : "r"(addr));
}
__device__ __forceinline__ void mma_bf16(float (&c)[4], const uint32_t (&a)[4],
                                         uint32_t b0, uint32_t b1) {
    asm volatile(
        "mma.sync.aligned.m16n8k16.row.col.f32.bf16.bf16.f32 "
        "{%0,%1,%2,%3}, {%4,%5,%6,%7}, {%8,%9}, {%0,%1,%2,%3};"
        : "+f"(c[0]), "+f"(c[1]), "+f"(c[2]), "+f"(c[3])
        : "r"(a[0]), "r"(a[1]), "r"(a[2]), "r"(a[3]), "r"(b0), "r"(b1));
}

// ---------------- barriers -----------------------------------------------------
// per-direction: 64 CTAs of one direction; all: full 128-CTA grid.
__device__ __forceinline__ void bar_wait(unsigned* cnt, unsigned &target, unsigned inc) {
    __syncthreads();
    if (threadIdx.x == 0) {
        __threadfence();                       // release this CTA's global stores
        atomicAdd(cnt, 1u);
        target += inc;
        while (*(volatile unsigned*)cnt < target) { }
        __threadfence();                       // acquire: invalidate stale L1
    }
    __syncthreads();
}

// ---------------- block stats: static-shared version (phaseA kernels) ----------
template <int NW>
__device__ __forceinline__ void block_stats(float s, float q, float invN,
                                            float &mu, float &rs) {
    __shared__ float redS[NW], redQ[NW], bc[2];
    int t = threadIdx.x;
    __syncthreads();
#pragma unroll
    for (int o = 16; o > 0; o >>= 1) {
        s += __shfl_xor_sync(0xFFFFFFFFu, s, o);
        q += __shfl_xor_sync(0xFFFFFFFFu, q, o);
    }
    if ((t & 31) == 0) { redS[t >> 5] = s; redQ[t >> 5] = q; }
    __syncthreads();
    if (t == 0) {
        float S = 0.f, Q = 0.f;
#pragma unroll
        for (int i = 0; i < NW; i++) { S += redS[i]; Q += redQ[i]; }
        float m = S * invN;
        bc[0] = m;
        bc[1] = rsqrtf(Q * invN - m * m + 1e-5f);
    }
    __syncthreads();
    mu = bc[0]; rs = bc[1];
}

// dynamic-scratch version for the scan kernel (512 threads = 16 warps)
__device__ __forceinline__ void block_stats_d(float s, float q, float invN,
                                              float &mu, float &rs, float* red) {
    int t = threadIdx.x;
    __syncthreads();
#pragma unroll
    for (int o = 16; o > 0; o >>= 1) {
        s += __shfl_xor_sync(0xFFFFFFFFu, s, o);
        q += __shfl_xor_sync(0xFFFFFFFFu, q, o);
    }
    if ((t & 31) == 0) { red[t >> 5] = s; red[16 + (t >> 5)] = q; }
    __syncthreads();
    if (t == 0) {
        float S = 0.f, Q = 0.f;
#pragma unroll
        for (int i = 0; i < 16; i++) { S += red[i]; Q += red[16 + i]; }
        float m = S * invN;
        red[32] = m;
        red[33] = rsqrtf(Q * invN - m * m + 1e-5f);
    }
    __syncthreads();
    mu = red[32]; rs = red[33];
}

// ================= Phase A: raw x @ W_ih0^T (FFMA version; at chip floor) ======
__global__ void __launch_bounds__(256, 2) phaseA_gemm(const float* __restrict__ x,
                                                      const float* __restrict__ w_ih0) {
    __shared__ float xs[64][68];
    __shared__ float ws[64][68];
    int r = blockIdx.x;
    int d = r / (SS * 32);
    int rem = r % (SS * 32);
    int s = rem / 32;
    int g0 = (rem % 32) * 64;

    int t = threadIdx.x;
    int tb = t & 15;
    int tg = t >> 4;

    float acc[4][4];
#pragma unroll
    for (int i = 0; i < 4; i++)
#pragma unroll
        for (int j = 0; j < 4; j++) acc[i][j] = 0.f;

    for (int kt = 0; kt < EE / 64; kt++) {
        int k0 = kt * 64;
#pragma unroll
        for (int i = 0; i < 4; i++) {
            int fi = t + 256 * i;
            int b = fi >> 4, kq = fi & 15;
            *(float4*)&xs[b][kq * 4] =
                *(const float4*)(x + ((size_t)b * SS + s) * EE + k0 + kq * 4);
        }
#pragma unroll
        for (int i = 0; i < 4; i++) {
            int fi = t + 256 * i;
            int gg = fi >> 4, kq = fi & 15;
            *(float4*)&ws[gg][kq * 4] =
                *(const float4*)(w_ih0 + ((size_t)d * GG + g0 + gg) * EE + k0 + kq * 4);
        }
        __syncthreads();
#pragma unroll 4
        for (int k = 0; k < 64; k += 4) {
            float4 wv[4];
#pragma unroll
            for (int j = 0; j < 4; j++) wv[j] = *(float4*)&ws[tg + 16 * j][k];
#pragma unroll
            for (int i = 0; i < 4; i++) {
                float4 hv = *(float4*)&xs[tb + 16 * i][k];
#pragma unroll
                for (int j = 0; j < 4; j++) {
                    acc[i][j] += hv.x * wv[j].x + hv.y * wv[j].y
                               + hv.z * wv[j].z + hv.w * wv[j].w;
                }
            }
        }
        __syncthreads();
    }
#pragma unroll
    for (int i = 0; i < 4; i++) {
        int b = tb + 16 * i;
#pragma unroll
        for (int j = 0; j < 4; j++)
            g_gih0[d][s][b][g0 + tg + 16 * j] = acc[i][j];
    }
}

// ================= Phase A LN (unchanged) ======================================
__global__ void __launch_bounds__(256) phaseA_ln(const float* __restrict__ gam,
                                                 const float* __restrict__ bet) {
    int r = blockIdx.x;
    int d = r / (SS * BB);
    int rem = r % (SS * BB);
    int s = rem / BB;
    int b = rem % BB;
    float* row = &g_gih0[d][s][b][0];
    int t = threadIdx.x;
    float v[8];
    float sum = 0.f, sq = 0.f;
#pragma unroll
    for (int i = 0; i < 8; i++) {
        v[i] = row[t + 256 * i];
        sum += v[i]; sq += v[i] * v[i];
    }
    float mu, rs;
    block_stats<8>(sum, sq, 1.0f / GG, mu, rs);
    const float* gm = gam + d * GG;
    const float* bt = bet + d * GG;
#pragma unroll
    for (int i = 0; i < 8; i++) {
        int g = t + 256 * i;
        row[g] = (v[i] - mu) * rs * gm[g] + bt[g];
    }
}

// ================= scan-kernel smem layout (byte offsets into dynbuf) ==========
#define A_OFF 256
#define AREG_B 73728
#define W_OFF (A_OFF + AREG_B)
#define WSPL_B 33280
#define CW_OFF (A_OFF + 132096)
#define P_OFF 198400
#define SCAN_SMEM_BYTES (P_OFF + 28672)

// convert this CTA's 32 W rows (fp32, K=512) into bf16 hi/mid/lo padded tiles
__device__ void loadW_bf16(unsigned char* dyn, const float* __restrict__ Wg) {
    int t = threadIdx.x;
    __nv_bfloat16* w0 = (__nv_bfloat16*)(dyn + W_OFF);
    __nv_bfloat16* w1 = (__nv_bfloat16*)(dyn + W_OFF + WSPL_B);
    __nv_bfloat16* w2 = (__nv_bfloat16*)(dyn + W_OFF + 2 * WSPL_B);
#pragma unroll
    for (int i = 0; i < 32; i++) {
        int idx = t + 512 * i;            // g = idx>>9, k = idx&511
        int g = idx >> 9, k = idx & 511;
        float v = Wg[(size_t)g * HH + k];
        __nv_bfloat16 hi = __float2bfloat16(v);
        float r1 = v - __bfloat162float(hi);
        __nv_bfloat16 mid = __float2bfloat16(r1);
        float r2 = r1 - __bfloat162float(mid);
        w0[g * 520 + k] = hi;
        w1[g * 520 + k] = mid;
        w2[g * 520 + k] = __float2bfloat16(r2);
    }
}

// ================= tensor-core step GEMM (mma.sync, 6-term bf16 3-way split) ===
__device__ void step_gemm_mma(int d, int cb, unsigned char* dyn, uint32_t base_u) {
    int t = threadIdx.x;
    int lane = t & 31, w = t >> 5;
    int mh = w >> 3, ks = w & 7;
    int q = lane >> 3, rr = lane & 7;
    int gid = lane >> 2, tid2 = lane & 3;
    uint32_t hs_u = base_u + A_OFF;
    uint32_t ws_u = base_u + W_OFF;

    float c[2][4][4];
#pragma unroll
    for (int mi = 0; mi < 2; mi++)
#pragma unroll
        for (int nj = 0; nj < 4; nj++)
#pragma unroll
            for (int e = 0; e < 4; e++) c[mi][nj][e] = 0.f;

    int arow = mh * 32 + (q & 1) * 8 + rr;
    int acol = (q >> 1) * 8;
    int brow = (q >> 1) * 8 + rr;
    int bcol = (q & 1) * 8;

#pragma unroll
    for (int p = 0; p < 3; p++) {
        __syncthreads();
        {   // fill h split p
            const float4* src = (const float4*)&g_hbf[d][p][0][0];
            __nv_bfloat16* hdst = (__nv_bfloat16*)(dyn + A_OFF);
#pragma unroll
            for (int i = 0; i < 8; i++) {
                int idx = t + 512 * i;
                int row = idx >> 6, cc = idx & 63;
                *(float4*)(hdst + row * 520 + cc * 8) = src[idx];
            }
        }
        __syncthreads();
        const int nB = 3 - p;
#pragma unroll
        for (int kk = 0; kk < 4; kk++) {
            int k = ks * 64 + kk * 16;
            uint32_t a[2][4];
#pragma unroll
            for (int mi = 0; mi < 2; mi++)
                ldm_x4(a[mi], hs_u + (uint32_t)(((arow + mi * 16) * 520 + k + acol) * 2));
#pragma unroll
            for (int wb = 0; wb < 3; wb++) {
                if (wb >= nB) break;
                uint32_t Bb = ws_u + (uint32_t)wb * WSPL_B;
                uint32_t bf[2][4];
#pragma unroll
                for (int njp = 0; njp < 2; njp++)
                    ldm_x4(bf[njp], Bb + (uint32_t)(((brow + njp * 16) * 520 + k + bcol) * 2));
#pragma unroll
                for (int mi = 0; mi < 2; mi++) {
                    mma_bf16(c[mi][0], a[mi], bf[0][0], bf[0][1]);
                    mma_bf16(c[mi][1], a[mi], bf[0][2], bf[0][3]);
                    mma_bf16(c[mi][2], a[mi], bf[1][0], bf[1][1]);
                    mma_bf16(c[mi][3], a[mi], bf[1][2], bf[1][3]);
                }
            }
        }
    }
    __syncthreads();

    float* scr = (float*)(dyn + A_OFF);
#pragma unroll
    for (int mi = 0; mi < 2; mi++)
#pragma unroll
        for (int nj = 0; nj < 4; nj++) {
            int b = mh * 32 + mi * 16 + gid;
            int n = nj * 8 + tid2 * 2;
            scr[ks * 2304 + b * 36 + n]           = c[mi][nj][0];
            scr[ks * 2304 + b * 36 + n + 1]       = c[mi][nj][1];
            scr[ks * 2304 + (b + 8) * 36 + n]     = c[mi][nj][2];
            scr[ks * 2304 + (b + 8) * 36 + n + 1] = c[mi][nj][3];
        }
    __syncthreads();
#pragma unroll
    for (int i = 0; i < 4; i++) {
        int e = t + 512 * i;
        int b = e >> 5, n = e & 31;
        float s = 0.f;
#pragma unroll
        for (int p = 0; p < 8; p++) s += scr[p * 2304 + b * 36 + n];
        g_u[d][b][cb * 32 + n] = s;
    }
}

// ---------------- fp32 FFMA path for the one-time concat GEMM -----------------
__device__ __forceinline__ void load_Wf(float (*ws)[516], const float* __restrict__ Wbase,
                                        int rowStride, int colOff) {
    int t = threadIdx.x;
#pragma unroll
    for (int i = 0; i < 8; i++) {
        int fi = t + 512 * i;
        int g = fi >> 7, kq = fi & 127;
        *(float4*)&ws[g][kq * 4] =
            *(const float4*)(Wbase + (size_t)g * rowStride + colOff + kq * 4);
    }
}
__device__ __forceinline__ void load_hf(float (*hs)[516], const float* __restrict__ src) {
    int t = threadIdx.x;
#pragma unroll
    for (int i = 0; i < 16; i++) {
        int fi = t + 512 * i;
        int b = fi >> 7, kq = fi & 127;
        *(float4*)&hs[b][kq * 4] = *(const float4*)(src + (size_t)b * HH + kq * 4);
    }
}
__device__ __forceinline__ void gemm_ffma(float (*hs)[516], float (*ws)[516],
                                          float (&acc)[4][2]) {
    int t = threadIdx.x;
    int half = t >> 8;
    int tl = t & 255;
    int tb = tl & 15;
    int tg = tl >> 4;
    const int kk0 = half << 8;
#pragma unroll 4
    for (int k = 0; k < 256; k += 8) {
        float4 w0a = *(const float4*)&ws[2 * tg][kk0 + k];
        float4 w1a = *(const float4*)&ws[2 * tg + 1][kk0 + k];
        float4 w0b = *(const float4*)&ws[2 * tg][kk0 + k + 4];
        float4 w1b = *(const float4*)&ws[2 * tg + 1][kk0 + k + 4];
        float4 ha[4], hb[4];
#pragma unroll
        for (int i = 0; i < 4; i++) {
            ha[i] = *(const float4*)&hs[tb + 16 * i][kk0 + k];
            hb[i] = *(const float4*)&hs[tb + 16 * i][kk0 + k + 4];
        }
#pragma unroll
        for (int i = 0; i < 4; i++) {
            acc[i][0] += ha[i].x * w0a.x + ha[i].y * w0a.y + ha[i].z * w0a.z + ha[i].w * w0a.w;
            acc[i][1] += ha[i].x * w1a.x + ha[i].y * w1a.y + ha[i].z * w1a.z + ha[i].w * w1a.w;
        }
#pragma unroll
        for (int i = 0; i < 4; i++) {
            acc[i][0] += hb[i].x * w0b.x + hb[i].y * w0b.y + hb[i].z * w0b.z + hb[i].w * w0b.w;
            acc[i][1] += hb[i].x * w1b.x + hb[i].y * w1b.y + hb[i].z * w1b.z + hb[i].w * w1b.w;
        }
    }
}
__device__ __forceinline__ void reduce_store_u(float* scratch, int d, int chunk,
                                               float (&acc)[4][2]) {
    int t = threadIdx.x;
    int half = t >> 8;
    int tl = t & 255;
    int tb = tl & 15, tg = tl >> 4;
    __syncthreads();
    if (half == 1) {
#pragma unroll
        for (int i = 0; i < 4; i++) {
            int b = tb + 16 * i;
            scratch[(2 * tg) * 64 + b]     = acc[i][0];
            scratch[(2 * tg + 1) * 64 + b] = acc[i][1];
        }
    }
    __syncthreads();
    if (half == 0) {
#pragma unroll
        for (int i = 0; i < 4; i++) {
            int b = tb + 16 * i;
            float2 o;
            o.x = acc[i][0] + scratch[(2 * tg) * 64 + b];
            o.y = acc[i][1] + scratch[(2 * tg + 1) * 64 + b];
            *(float2*)&g_u[d][b][chunk * 32 + 2 * tg] = o;
        }
    }
}

// ================= pointwise: CTA owns row (d, b); 1 hidden unit per thread ====
__device__ void step_point(int d, int b, const float* gihr, const float* g1row,
                           int useG1, float* red, const float* hhg, const float* hhb,
                           const float* hog, const float* hob, float &c,
                           float* __restrict__ outrow) {
    int j = threadIdx.x;
    const float* urow = &g_u[d][b][0];
    float uv[4], gv4[4];
    float s = 0.f, q = 0.f;
#pragma unroll
    for (int m = 0; m < 4; m++) {
        uv[m] = urow[j + 512 * m];
        s += uv[m]; q += uv[m] * uv[m];
        gv4[m] = useG1 ? g1row[j + 512 * m] : gihr[m];
    }
    float mu, rs;
    block_stats_d(s, q, 1.0f / GG, mu, rs, red);

    float vi = gv4[0] + (uv[0] - mu) * rs * hhg[j]        + hhb[j];
    float vf = gv4[1] + (uv[1] - mu) * rs * hhg[512 + j]  + hhb[512 + j];
    float vo = gv4[2] + (uv[2] - mu) * rs * hhg[1024 + j] + hhb[1024 + j];
    float vg = gv4[3] + (uv[3] - mu) * rs * hhg[1536 + j] + hhb[1536 + j];
    float ig = sigmoidf_(vi);
    float fg = sigmoidf_(vf);
    float og = sigmoidf_(vo);
    float gg = tanhf_(vg);
    float cn = fg * c + ig * gg;

    float muc, rsc;
    block_stats_d(cn, cn * cn, 1.0f / HH, muc, rsc, red);
    float hval = og * tanhf_((cn - muc) * rsc * hog[j] + hob[j]);
    c = cn;
    g_h[d][b][j] = hval;
    __nv_bfloat16 hi = __float2bfloat16(hval);
    float r1 = hval - __bfloat162float(hi);
    __nv_bfloat16 mid = __float2bfloat16(r1);
    float r2 = r1 - __bfloat162float(mid);
    g_hbf[d][0][b][j] = hi;
    g_hbf[d][1][b][j] = mid;
    g_hbf[d][2][b][j] = __float2bfloat16(r2);
    if (outrow) outrow[j] = hval;
}

// layer-1 input LN into smem g1row; reset h (fp32 + bf16) for layer 1
__device__ void g1_finalize(int d, int b, float* g1row, float* red,
                            const float* __restrict__ ihg, const float* __restrict__ ihb) {
    int t = threadIdx.x;
    const float* urow = &g_u[d][b][0];
    float uv[4];
    float s = 0.f, q = 0.f;
#pragma unroll
    for (int m = 0; m < 4; m++) {
        uv[m] = urow[t + 512 * m];
        s += uv[m]; q += uv[m] * uv[m];
    }
    float mu, rs;
    block_stats_d(s, q, 1.0f / GG, mu, rs, red);
#pragma unroll
    for (int m = 0; m < 4; m++) {
        int g = t + 512 * m;
        g1row[g] = (uv[m] - mu) * rs * ihg[g] + ihb[g];
    }
    g_h[d][b][t] = 0.f;
    g_hbf[d][0][b][t] = __float2bfloat16(0.f);
    g_hbf[d][1][b][t] = __float2bfloat16(0.f);
    g_hbf[d][2][b][t] = __float2bfloat16(0.f);
}

__device__ void load_params(float* hhg, float* hhb, float* hog, float* hob,
                            const float* shhg, const float* shhb,
                            const float* shog, const float* shob) {
    int t = threadIdx.x;
#pragma unroll
    for (int i = 0; i < 4; i++) {
        int j = t + 512 * i;
        hhg[j] = shhg[j];
        hhb[j] = shhb[j];
    }
    hog[t] = shog[t];
    hob[t] = shob[t];
}

// ================= persistent recurrent kernel ================================
__global__ void __launch_bounds__(512, 1) scan_kernel(
    const float* __restrict__ w_hh0,
    const float* __restrict__ ln_hh0_g, const float* __restrict__ ln_hh0_b,
    const float* __restrict__ ln_ho0_g, const float* __restrict__ ln_ho0_b,
    const float* __restrict__ w_ih1, const float* __restrict__ w_hh1,
    const float* __restrict__ ln_ih1_g, const float* __restrict__ ln_ih1_b,
    const float* __restrict__ ln_hh1_g, const float* __restrict__ ln_hh1_b,
    const float* __restrict__ ln_ho1_g, const float* __restrict__ ln_ho1_b,
    float* __restrict__ out) {
    extern __shared__ unsigned char dynbuf[];
    uint32_t base_u = smem_u32(dynbuf);
    float* red = (float*)dynbuf;
    float* P = (float*)(dynbuf + P_OFF);
    float* hhg = P;
    float* hhb = P + 2048;
    float* hog = P + 4096;
    float* hob = P + 4608;
    float* g1row = P + 5120;

    int r = blockIdx.x;
    int d = r >> 6;
    int cb = r & 63;
    int t = threadIdx.x;
    unsigned targ_d = 0;       // per-direction barrier target
    unsigned targ_all = 0;     // full-grid barrier target
    unsigned* dcnt = &g_bar_d[d][0];
    float c = 0.f;

    // one-time setup
    loadW_bf16(dynbuf, w_hh0 + ((size_t)d * GG + cb * 32) * HH);
    load_params(hhg, hhb, hog, hob, ln_hh0_g + d * GG, ln_hh0_b + d * GG,
                ln_ho0_g + d * HH, ln_ho0_b + d * HH);
    g_h[d][cb][t] = 0.f;
    g_hbf[d][0][cb][t] = __float2bfloat16(0.f);
    g_hbf[d][1][cb][t] = __float2bfloat16(0.f);
    g_hbf[d][2][cb][t] = __float2bfloat16(0.f);
    bar_wait(dcnt, targ_d, 64);

    // ---- layer 0 scan (per-direction barriers; dirs fully independent) ----
    for (int st = 0; st < SS; st++) {
        int te = (d == 0) ? st : (SS - 1 - st);
        const float* gptr = &g_gih0[d][te][cb][0];
        float gihr[4];
#pragma unroll
        for (int m = 0; m < 4; m++) gihr[m] = gptr[t + 512 * m];
        step_gemm_mma(d, cb, dynbuf, base_u);
        bar_wait(dcnt, targ_d, 64);
        step_point(d, cb, gihr, g1row, 0, red, hhg, hhb, hog, hob, c, nullptr);
        bar_wait(dcnt, targ_d, 64);
    }

    // ---- join: concat GEMM reads BOTH directions' h ----
    bar_wait(&g_bar_all, targ_all, 128);
    {
        float (*hsf)[516] = (float (*)[516])(dynbuf + A_OFF);
        float (*wsf)[516] = (float (*)[516])(dynbuf + CW_OFF);
        float acc[4][2];
#pragma unroll
        for (int i = 0; i < 4; i++) { acc[i][0] = 0.f; acc[i][1] = 0.f; }
        load_Wf(wsf, w_ih1 + ((size_t)d * GG + cb * 32) * (2 * HH), 2 * HH, 0);
        load_hf(hsf, &g_h[0][0][0]);
        __syncthreads();
        gemm_ffma(hsf, wsf, acc);
        __syncthreads();
        load_Wf(wsf, w_ih1 + ((size_t)d * GG + cb * 32) * (2 * HH), 2 * HH, HH);
        load_hf(hsf, &g_h[1][0][0]);
        __syncthreads();
        gemm_ffma(hsf, wsf, acc);
        reduce_store_u((float*)(dynbuf + A_OFF), d, cb, acc);
    }
    bar_wait(dcnt, targ_d, 64);
    g1_finalize(d, cb, g1row, red, ln_ih1_g + d * GG, ln_ih1_b + d * GG);
    c = 0.f;
    __syncthreads();
    loadW_bf16(dynbuf, w_hh1 + ((size_t)d * GG + cb * 32) * HH);
    load_params(hhg, hhb, hog, hob, ln_hh1_g + d * GG, ln_hh1_b + d * GG,
                ln_ho1_g + d * HH, ln_ho1_b + d * HH);
    bar_wait(dcnt, targ_d, 64);

    // ---- layer 1 scan (per-direction) ----
    for (int st = 0; st < SS; st++) {
        step_gemm_mma(d, cb, dynbuf, base_u);
        bar_wait(dcnt, targ_d, 64);
        bool last = (st == SS - 1);
        step_point(d, cb, nullptr, g1row, 1, red, hhg, hhb, hog, hob, c,
                   last ? (out + (size_t)cb * 1024 + d * 512) : nullptr);
        if (!last) bar_wait(dcnt, targ_d, 64);
    }

    // ---- exit protocol: last CTA resets all barrier counters ----
    __syncthreads();
    if (t == 0) {
        __threadfence();
        unsigned n = atomicAdd(&g_excnt, 1u) + 1;
        if (n == NCTA) {
            g_bar_d[0][0] = 0;
            g_bar_d[1][0] = 0;
            g_bar_all = 0;
            g_excnt = 0;
            __threadfence();
        }
    }
}

// =============================================================================
extern "C" void kernel_launch(void* const* d_in, const int* in_sizes, int n_in,
                              void* d_out, int out_size) {
    const float* x        = (const float*)d_in[0];
    // d_in[1] = text_length (unused by the reference forward)
    const float* w_ih0    = (const float*)d_in[2];
    const float* w_hh0    = (const float*)d_in[3];
    const float* ln_ih0_g = (const float*)d_in[4];
    const float* ln_ih0_b = (const float*)d_in[5];
    const float* ln_hh0_g = (const float*)d_in[6];
    const float* ln_hh0_b = (const float*)d_in[7];
    const float* ln_ho0_g = (const float*)d_in[8];
    const float* ln_ho0_b = (const float*)d_in[9];
    const float* w_ih1    = (const float*)d_in[10];
    const float* w_hh1    = (const float*)d_in[11];
    const float* ln_ih1_g = (const float*)d_in[12];
    const float* ln_ih1_b = (const float*)d_in[13];
    const float* ln_hh1_g = (const float*)d_in[14];
    const float* ln_hh1_b = (const float*)d_in[15];
    const float* ln_ho1_g = (const float*)d_in[16];
    const float* ln_ho1_b = (const float*)d_in[17];
    float* out = (float*)d_out;

    static int smem_set = 0;
    if (!smem_set) {
        cudaFuncSetAttribute(scan_kernel, cudaFuncAttributeMaxDynamicSharedMemorySize,
                             SCAN_SMEM_BYTES);
        smem_set = 1;
    }

    phaseA_gemm<<<2 * SS * 32, 256>>>(x, w_ih0);
    phaseA_ln<<<2 * SS * BB, 256>>>(ln_ih0_g, ln_ih0_b);
    scan_kernel<<<NCTA, 512, SCAN_SMEM_BYTES>>>(
        w_hh0, ln_hh0_g, ln_hh0_b, ln_ho0_g, ln_ho0_b,
        w_ih1, w_hh1, ln_ih1_g, ln_ih1_b,
        ln_hh1_g, ln_hh1_b, ln_ho1_g, ln_ho1_b, out);
}

// round 15
// speedup vs baseline: 1.5093x; 1.5093x over previous
#include <cuda_runtime.h>
#include <cuda_bf16.h>
#include <cstdint>

#define BB 64
#define SS 48
#define EE 512
#define HH 512
#define GG 2048
#define NCTA 128

// ---------------- persistent device scratch (no allocs allowed) ----------------
__device__ float g_gih0[2][SS][BB][GG];   // LN(x @ W_ih0^T), both dirs  (~50MB)
__device__ float g_u[2][BB][GG];          // per-step h @ W_hh^T (raw)
__device__ float g_h[2][BB][HH];
__device__ __nv_bfloat16 g_hbf[2][3][BB][HH];  // [dir][hi/mid/lo] bf16 3-way split of h
__device__ unsigned g_bar_d[2][32];       // per-direction barrier counters (padded)
__device__ unsigned g_bar_all = 0;        // full-grid join barrier
__device__ unsigned g_excnt = 0;

// fast activations (__expf err ~2^-22; verified in R12: no rel_err movement)
__device__ __forceinline__ float sigmoidf_(float x) {
    return __fdividef(1.0f, 1.0f + __expf(-x));
}
__device__ __forceinline__ float tanhf_(float x) {
    float xx = fminf(fmaxf(x, -15.f), 15.f);
    float e = __expf(2.f * xx);
    return __fdividef(e - 1.f, e + 1.f);
}

__device__ __forceinline__ uint32_t smem_u32(const void* p) {
    uint32_t a;
    asm("{ .reg .u64 t; cvta.to.shared.u64 t, %1; cvt.u32.u64 %0, t; }" : "=r"(a) : "l"(p));
    return a;
}

// ---------------- mma.sync helpers (baseline PTX; valid on sm_103) -------------
__device__ __forceinline__ void ldm_x4(uint32_t (&r)[4], uint32_t addr) {
    asm volatile("ldmatrix.sync.aligned.m8n8.x4.shared.b16 {%0,%1,%2,%3}, [%4];"
                 : "=r"(r[0]), "=r"(r[1]), "=r"(r[2]), "=r"(r[3]) : "r"(addr));
}
__device__ __forceinline__ void mma_bf16(float (&c)[4], const uint32_t (&a)[4],
                                         uint32_t b0, uint32_t b1) {
    asm volatile(
        "mma.sync.aligned.m16n8k16.row.col.f32.bf16.bf16.f32 "
        "{%0,%1,%2,%3}, {%4,%5,%6,%7}, {%8,%9}, {%0,%1,%2,%3};"
        : "+f"(c[0]), "+f"(c[1]), "+f"(c[2]), "+f"(c[3])
        : "r"(a[0]), "r"(a[1]), "r"(a[2]), "r"(a[3]), "r"(b0), "r"(b1));
}

// ---------------- barriers -----------------------------------------------------
// per-direction: 64 CTAs of one direction; all: full 128-CTA grid.
// __nanosleep backoff cuts L2 poll traffic while spinning (power/NOC pressure).
__device__ __forceinline__ void bar_wait(unsigned* cnt, unsigned &target, unsigned inc) {
    __syncthreads();
    if (threadIdx.x == 0) {
        __threadfence();                       // release this CTA's global stores
        atomicAdd(cnt, 1u);
        target += inc;
        while (*(volatile unsigned*)cnt < target) { __nanosleep(40); }
        __threadfence();                       // acquire: invalidate stale L1
    }
    __syncthreads();
}

// ---------------- block stats: static-shared version (phaseA kernels) ----------
template <int NW>
__device__ __forceinline__ void block_stats(float s, float q, float invN,
                                            float &mu, float &rs) {
    __shared__ float redS[NW], redQ[NW], bc[2];
    int t = threadIdx.x;
    __syncthreads();
#pragma unroll
    for (int o = 16; o > 0; o >>= 1) {
        s += __shfl_xor_sync(0xFFFFFFFFu, s, o);
        q += __shfl_xor_sync(0xFFFFFFFFu, q, o);
    }
    if ((t & 31) == 0) { redS[t >> 5] = s; redQ[t >> 5] = q; }
    __syncthreads();
    if (t == 0) {
        float S = 0.f, Q = 0.f;
#pragma unroll
        for (int i = 0; i < NW; i++) { S += redS[i]; Q += redQ[i]; }
        float m = S * invN;
        bc[0] = m;
        bc[1] = rsqrtf(Q * invN - m * m + 1e-5f);
    }
    __syncthreads();
    mu = bc[0]; rs = bc[1];
}

// dynamic-scratch version for the scan kernel (512 threads = 16 warps)
__device__ __forceinline__ void block_stats_d(float s, float q, float invN,
                                              float &mu, float &rs, float* red) {
    int t = threadIdx.x;
    __syncthreads();
#pragma unroll
    for (int o = 16; o > 0; o >>= 1) {
        s += __shfl_xor_sync(0xFFFFFFFFu, s, o);
        q += __shfl_xor_sync(0xFFFFFFFFu, q, o);
    }
    if ((t & 31) == 0) { red[t >> 5] = s; red[16 + (t >> 5)] = q; }
    __syncthreads();
    if (t == 0) {
        float S = 0.f, Q = 0.f;
#pragma unroll
        for (int i = 0; i < 16; i++) { S += red[i]; Q += red[16 + i]; }
        float m = S * invN;
        red[32] = m;
        red[33] = rsqrtf(Q * invN - m * m + 1e-5f);
    }
    __syncthreads();
    mu = red[32]; rs = red[33];
}

// ================= Phase A: raw x @ W_ih0^T (FFMA version; at chip floor) ======
__global__ void __launch_bounds__(256, 2) phaseA_gemm(const float* __restrict__ x,
                                                      const float* __restrict__ w_ih0) {
    __shared__ float xs[64][68];
    __shared__ float ws[64][68];
    int r = blockIdx.x;
    int d = r / (SS * 32);
    int rem = r % (SS * 32);
    int s = rem / 32;
    int g0 = (rem % 32) * 64;

    int t = threadIdx.x;
    int tb = t & 15;
    int tg = t >> 4;

    float acc[4][4];
#pragma unroll
    for (int i = 0; i < 4; i++)
#pragma unroll
        for (int j = 0; j < 4; j++) acc[i][j] = 0.f;

    for (int kt = 0; kt < EE / 64; kt++) {
        int k0 = kt * 64;
#pragma unroll
        for (int i = 0; i < 4; i++) {
            int fi = t + 256 * i;
            int b = fi >> 4, kq = fi & 15;
            *(float4*)&xs[b][kq * 4] =
                *(const float4*)(x + ((size_t)b * SS + s) * EE + k0 + kq * 4);
        }
#pragma unroll
        for (int i = 0; i < 4; i++) {
            int fi = t + 256 * i;
            int gg = fi >> 4, kq = fi & 15;
            *(float4*)&ws[gg][kq * 4] =
                *(const float4*)(w_ih0 + ((size_t)d * GG + g0 + gg) * EE + k0 + kq * 4);
        }
        __syncthreads();
#pragma unroll 4
        for (int k = 0; k < 64; k += 4) {
            float4 wv[4];
#pragma unroll
            for (int j = 0; j < 4; j++) wv[j] = *(float4*)&ws[tg + 16 * j][k];
#pragma unroll
            for (int i = 0; i < 4; i++) {
                float4 hv = *(float4*)&xs[tb + 16 * i][k];
#pragma unroll
                for (int j = 0; j < 4; j++) {
                    acc[i][j] += hv.x * wv[j].x + hv.y * wv[j].y
                               + hv.z * wv[j].z + hv.w * wv[j].w;
                }
            }
        }
        __syncthreads();
    }
#pragma unroll
    for (int i = 0; i < 4; i++) {
        int b = tb + 16 * i;
#pragma unroll
        for (int j = 0; j < 4; j++)
            g_gih0[d][s][b][g0 + tg + 16 * j] = acc[i][j];
    }
}

// ================= Phase A LN (unchanged) ======================================
__global__ void __launch_bounds__(256) phaseA_ln(const float* __restrict__ gam,
                                                 const float* __restrict__ bet) {
    int r = blockIdx.x;
    int d = r / (SS * BB);
    int rem = r % (SS * BB);
    int s = rem / BB;
    int b = rem % BB;
    float* row = &g_gih0[d][s][b][0];
    int t = threadIdx.x;
    float v[8];
    float sum = 0.f, sq = 0.f;
#pragma unroll
    for (int i = 0; i < 8; i++) {
        v[i] = row[t + 256 * i];
        sum += v[i]; sq += v[i] * v[i];
    }
    float mu, rs;
    block_stats<8>(sum, sq, 1.0f / GG, mu, rs);
    const float* gm = gam + d * GG;
    const float* bt = bet + d * GG;
#pragma unroll
    for (int i = 0; i < 8; i++) {
        int g = t + 256 * i;
        row[g] = (v[i] - mu) * rs * gm[g] + bt[g];
    }
}

// ================= scan-kernel smem layout (byte offsets into dynbuf) ==========
#define A_OFF 256
#define AREG_B 73728
#define W_OFF (A_OFF + AREG_B)
#define WSPL_B 33280
#define CW_OFF (A_OFF + 132096)
#define P_OFF 198400
#define SCAN_SMEM_BYTES (P_OFF + 28672)

// convert this CTA's 32 W rows (fp32, K=512) into bf16 hi/mid/lo padded tiles
__device__ void loadW_bf16(unsigned char* dyn, const float* __restrict__ Wg) {
    int t = threadIdx.x;
    __nv_bfloat16* w0 = (__nv_bfloat16*)(dyn + W_OFF);
    __nv_bfloat16* w1 = (__nv_bfloat16*)(dyn + W_OFF + WSPL_B);
    __nv_bfloat16* w2 = (__nv_bfloat16*)(dyn + W_OFF + 2 * WSPL_B);
#pragma unroll
    for (int i = 0; i < 32; i++) {
        int idx = t + 512 * i;            // g = idx>>9, k = idx&511
        int g = idx >> 9, k = idx & 511;
        float v = Wg[(size_t)g * HH + k];
        __nv_bfloat16 hi = __float2bfloat16(v);
        float r1 = v - __bfloat162float(hi);
        __nv_bfloat16 mid = __float2bfloat16(r1);
        float r2 = r1 - __bfloat162float(mid);
        w0[g * 520 + k] = hi;
        w1[g * 520 + k] = mid;
        w2[g * 520 + k] = __float2bfloat16(r2);
    }
}

// ================= tensor-core step GEMM (mma.sync, 6-term bf16 3-way split) ===
__device__ void step_gemm_mma(int d, int cb, unsigned char* dyn, uint32_t base_u) {
    int t = threadIdx.x;
    int lane = t & 31, w = t >> 5;
    int mh = w >> 3, ks = w & 7;
    int q = lane >> 3, rr = lane & 7;
    int gid = lane >> 2, tid2 = lane & 3;
    uint32_t hs_u = base_u + A_OFF;
    uint32_t ws_u = base_u + W_OFF;

    float c[2][4][4];
#pragma unroll
    for (int mi = 0; mi < 2; mi++)
#pragma unroll
        for (int nj = 0; nj < 4; nj++)
#pragma unroll
            for (int e = 0; e < 4; e++) c[mi][nj][e] = 0.f;

    int arow = mh * 32 + (q & 1) * 8 + rr;
    int acol = (q >> 1) * 8;
    int brow = (q >> 1) * 8 + rr;
    int bcol = (q & 1) * 8;

#pragma unroll
    for (int p = 0; p < 3; p++) {
        __syncthreads();
        {   // fill h split p
            const float4* src = (const float4*)&g_hbf[d][p][0][0];
            __nv_bfloat16* hdst = (__nv_bfloat16*)(dyn + A_OFF);
#pragma unroll
            for (int i = 0; i < 8; i++) {
                int idx = t + 512 * i;
                int row = idx >> 6, cc = idx & 63;
                *(float4*)(hdst + row * 520 + cc * 8) = src[idx];
            }
        }
        __syncthreads();
        const int nB = 3 - p;
#pragma unroll
        for (int kk = 0; kk < 4; kk++) {
            int k = ks * 64 + kk * 16;
            uint32_t a[2][4];
#pragma unroll
            for (int mi = 0; mi < 2; mi++)
                ldm_x4(a[mi], hs_u + (uint32_t)(((arow + mi * 16) * 520 + k + acol) * 2));
#pragma unroll
            for (int wb = 0; wb < 3; wb++) {
                if (wb >= nB) break;
                uint32_t Bb = ws_u + (uint32_t)wb * WSPL_B;
                uint32_t bf[2][4];
#pragma unroll
                for (int njp = 0; njp < 2; njp++)
                    ldm_x4(bf[njp], Bb + (uint32_t)(((brow + njp * 16) * 520 + k + bcol) * 2));
#pragma unroll
                for (int mi = 0; mi < 2; mi++) {
                    mma_bf16(c[mi][0], a[mi], bf[0][0], bf[0][1]);
                    mma_bf16(c[mi][1], a[mi], bf[0][2], bf[0][3]);
                    mma_bf16(c[mi][2], a[mi], bf[1][0], bf[1][1]);
                    mma_bf16(c[mi][3], a[mi], bf[1][2], bf[1][3]);
                }
            }
        }
    }
    __syncthreads();

    float* scr = (float*)(dyn + A_OFF);
#pragma unroll
    for (int mi = 0; mi < 2; mi++)
#pragma unroll
        for (int nj = 0; nj < 4; nj++) {
            int b = mh * 32 + mi * 16 + gid;
            int n = nj * 8 + tid2 * 2;
            scr[ks * 2304 + b * 36 + n]           = c[mi][nj][0];
            scr[ks * 2304 + b * 36 + n + 1]       = c[mi][nj][1];
            scr[ks * 2304 + (b + 8) * 36 + n]     = c[mi][nj][2];
            scr[ks * 2304 + (b + 8) * 36 + n + 1] = c[mi][nj][3];
        }
    __syncthreads();
#pragma unroll
    for (int i = 0; i < 4; i++) {
        int e = t + 512 * i;
        int b = e >> 5, n = e & 31;
        float s = 0.f;
#pragma unroll
        for (int p = 0; p < 8; p++) s += scr[p * 2304 + b * 36 + n];
        g_u[d][b][cb * 32 + n] = s;
    }
}

// ---------------- fp32 FFMA path for the one-time concat GEMM -----------------
__device__ __forceinline__ void load_Wf(float (*ws)[516], const float* __restrict__ Wbase,
                                        int rowStride, int colOff) {
    int t = threadIdx.x;
#pragma unroll
    for (int i = 0; i < 8; i++) {
        int fi = t + 512 * i;
        int g = fi >> 7, kq = fi & 127;
        *(float4*)&ws[g][kq * 4] =
            *(const float4*)(Wbase + (size_t)g * rowStride + colOff + kq * 4);
    }
}
__device__ __forceinline__ void load_hf(float (*hs)[516], const float* __restrict__ src) {
    int t = threadIdx.x;
#pragma unroll
    for (int i = 0; i < 16; i++) {
        int fi = t + 512 * i;
        int b = fi >> 7, kq = fi & 127;
        *(float4*)&hs[b][kq * 4] = *(const float4*)(src + (size_t)b * HH + kq * 4);
    }
}
__device__ __forceinline__ void gemm_ffma(float (*hs)[516], float (*ws)[516],
                                          float (&acc)[4][2]) {
    int t = threadIdx.x;
    int half = t >> 8;
    int tl = t & 255;
    int tb = tl & 15;
    int tg = tl >> 4;
    const int kk0 = half << 8;
#pragma unroll 4
    for (int k = 0; k < 256; k += 8) {
        float4 w0a = *(const float4*)&ws[2 * tg][kk0 + k];
        float4 w1a = *(const float4*)&ws[2 * tg + 1][kk0 + k];
        float4 w0b = *(const float4*)&ws[2 * tg][kk0 + k + 4];
        float4 w1b = *(const float4*)&ws[2 * tg + 1][kk0 + k + 4];
        float4 ha[4], hb[4];
#pragma unroll
        for (int i = 0; i < 4; i++) {
            ha[i] = *(const float4*)&hs[tb + 16 * i][kk0 + k];
            hb[i] = *(const float4*)&hs[tb + 16 * i][kk0 + k + 4];
        }
#pragma unroll
        for (int i = 0; i < 4; i++) {
            acc[i][0] += ha[i].x * w0a.x + ha[i].y * w0a.y + ha[i].z * w0a.z + ha[i].w * w0a.w;
            acc[i][1] += ha[i].x * w1a.x + ha[i].y * w1a.y + ha[i].z * w1a.z + ha[i].w * w1a.w;
        }
#pragma unroll
        for (int i = 0; i < 4; i++) {
            acc[i][0] += hb[i].x * w0b.x + hb[i].y * w0b.y + hb[i].z * w0b.z + hb[i].w * w0b.w;
            acc[i][1] += hb[i].x * w1b.x + hb[i].y * w1b.y + hb[i].z * w1b.z + hb[i].w * w1b.w;
        }
    }
}
__device__ __forceinline__ void reduce_store_u(float* scratch, int d, int chunk,
                                               float (&acc)[4][2]) {
    int t = threadIdx.x;
    int half = t >> 8;
    int tl = t & 255;
    int tb = tl & 15, tg = tl >> 4;
    __syncthreads();
    if (half == 1) {
#pragma unroll
        for (int i = 0; i < 4; i++) {
            int b = tb + 16 * i;
            scratch[(2 * tg) * 64 + b]     = acc[i][0];
            scratch[(2 * tg + 1) * 64 + b] = acc[i][1];
        }
    }
    __syncthreads();
    if (half == 0) {
#pragma unroll
        for (int i = 0; i < 4; i++) {
            int b = tb + 16 * i;
            float2 o;
            o.x = acc[i][0] + scratch[(2 * tg) * 64 + b];
            o.y = acc[i][1] + scratch[(2 * tg + 1) * 64 + b];
            *(float2*)&g_u[d][b][chunk * 32 + 2 * tg] = o;
        }
    }
}

// ================= pointwise: CTA owns row (d, b); 1 hidden unit per thread ====
__device__ void step_point(int d, int b, const float* gihr, const float* g1row,
                           int useG1, float* red, const float* hhg, const float* hhb,
                           const float* hog, const float* hob, float &c,
                           float* __restrict__ outrow) {
    int j = threadIdx.x;
    const float* urow = &g_u[d][b][0];
    float uv[4], gv4[4];
    float s = 0.f, q = 0.f;
#pragma unroll
    for (int m = 0; m < 4; m++) {
        uv[m] = urow[j + 512 * m];
        s += uv[m]; q += uv[m] * uv[m];
        gv4[m] = useG1 ? g1row[j + 512 * m] : gihr[m];
    }
    float mu, rs;
    block_stats_d(s, q, 1.0f / GG, mu, rs, red);

    float vi = gv4[0] + (uv[0] - mu) * rs * hhg[j]        + hhb[j];
    float vf = gv4[1] + (uv[1] - mu) * rs * hhg[512 + j]  + hhb[512 + j];
    float vo = gv4[2] + (uv[2] - mu) * rs * hhg[1024 + j] + hhb[1024 + j];
    float vg = gv4[3] + (uv[3] - mu) * rs * hhg[1536 + j] + hhb[1536 + j];
    float ig = sigmoidf_(vi);
    float fg = sigmoidf_(vf);
    float og = sigmoidf_(vo);
    float gg = tanhf_(vg);
    float cn = fg * c + ig * gg;

    float muc, rsc;
    block_stats_d(cn, cn * cn, 1.0f / HH, muc, rsc, red);
    float hval = og * tanhf_((cn - muc) * rsc * hog[j] + hob[j]);
    c = cn;
    g_h[d][b][j] = hval;
    __nv_bfloat16 hi = __float2bfloat16(hval);
    float r1 = hval - __bfloat162float(hi);
    __nv_bfloat16 mid = __float2bfloat16(r1);
    float r2 = r1 - __bfloat162float(mid);
    g_hbf[d][0][b][j] = hi;
    g_hbf[d][1][b][j] = mid;
    g_hbf[d][2][b][j] = __float2bfloat16(r2);
    if (outrow) outrow[j] = hval;
}

// layer-1 input LN into smem g1row; reset h (fp32 + bf16) for layer 1
__device__ void g1_finalize(int d, int b, float* g1row, float* red,
                            const float* __restrict__ ihg, const float* __restrict__ ihb) {
    int t = threadIdx.x;
    const float* urow = &g_u[d][b][0];
    float uv[4];
    float s = 0.f, q = 0.f;
#pragma unroll
    for (int m = 0; m < 4; m++) {
        uv[m] = urow[t + 512 * m];
        s += uv[m]; q += uv[m] * uv[m];
    }
    float mu, rs;
    block_stats_d(s, q, 1.0f / GG, mu, rs, red);
#pragma unroll
    for (int m = 0; m < 4; m++) {
        int g = t + 512 * m;
        g1row[g] = (uv[m] - mu) * rs * ihg[g] + ihb[g];
    }
    g_h[d][b][t] = 0.f;
    g_hbf[d][0][b][t] = __float2bfloat16(0.f);
    g_hbf[d][1][b][t] = __float2bfloat16(0.f);
    g_hbf[d][2][b][t] = __float2bfloat16(0.f);
}

__device__ void load_params(float* hhg, float* hhb, float* hog, float* hob,
                            const float* shhg, const float* shhb,
                            const float* shog, const float* shob) {
    int t = threadIdx.x;
#pragma unroll
    for (int i = 0; i < 4; i++) {
        int j = t + 512 * i;
        hhg[j] = shhg[j];
        hhb[j] = shhb[j];
    }
    hog[t] = shog[t];
    hob[t] = shob[t];
}

// ================= persistent recurrent kernel ================================
__global__ void __launch_bounds__(512, 1) scan_kernel(
    const float* __restrict__ w_hh0,
    const float* __restrict__ ln_hh0_g, const float* __restrict__ ln_hh0_b,
    const float* __restrict__ ln_ho0_g, const float* __restrict__ ln_ho0_b,
    const float* __restrict__ w_ih1, const float* __restrict__ w_hh1,
    const float* __restrict__ ln_ih1_g, const float* __restrict__ ln_ih1_b,
    const float* __restrict__ ln_hh1_g, const float* __restrict__ ln_hh1_b,
    const float* __restrict__ ln_ho1_g, const float* __restrict__ ln_ho1_b,
    float* __restrict__ out) {
    extern __shared__ unsigned char dynbuf[];
    uint32_t base_u = smem_u32(dynbuf);
    float* red = (float*)dynbuf;
    float* P = (float*)(dynbuf + P_OFF);
    float* hhg = P;
    float* hhb = P + 2048;
    float* hog = P + 4096;
    float* hob = P + 4608;
    float* g1row = P + 5120;

    int r = blockIdx.x;
    int d = r >> 6;
    int cb = r & 63;
    int t = threadIdx.x;
    unsigned targ_d = 0;       // per-direction barrier target
    unsigned targ_all = 0;     // full-grid barrier target
    unsigned* dcnt = &g_bar_d[d][0];
    float c = 0.f;

    // one-time setup
    loadW_bf16(dynbuf, w_hh0 + ((size_t)d * GG + cb * 32) * HH);
    load_params(hhg, hhb, hog, hob, ln_hh0_g + d * GG, ln_hh0_b + d * GG,
                ln_ho0_g + d * HH, ln_ho0_b + d * HH);
    g_h[d][cb][t] = 0.f;
    g_hbf[d][0][cb][t] = __float2bfloat16(0.f);
    g_hbf[d][1][cb][t] = __float2bfloat16(0.f);
    g_hbf[d][2][cb][t] = __float2bfloat16(0.f);
    bar_wait(dcnt, targ_d, 64);

    // ---- layer 0 scan (per-direction barriers; dirs fully independent) ----
    for (int st = 0; st < SS; st++) {
        int te = (d == 0) ? st : (SS - 1 - st);
        const float* gptr = &g_gih0[d][te][cb][0];
        float gihr[4];
#pragma unroll
        for (int m = 0; m < 4; m++) gihr[m] = gptr[t + 512 * m];
        step_gemm_mma(d, cb, dynbuf, base_u);
        bar_wait(dcnt, targ_d, 64);
        step_point(d, cb, gihr, g1row, 0, red, hhg, hhb, hog, hob, c, nullptr);
        bar_wait(dcnt, targ_d, 64);
    }

    // ---- join: concat GEMM reads BOTH directions' h ----
    bar_wait(&g_bar_all, targ_all, 128);
    {
        float (*hsf)[516] = (float (*)[516])(dynbuf + A_OFF);
        float (*wsf)[516] = (float (*)[516])(dynbuf + CW_OFF);
        float acc[4][2];
#pragma unroll
        for (int i = 0; i < 4; i++) { acc[i][0] = 0.f; acc[i][1] = 0.f; }
        load_Wf(wsf, w_ih1 + ((size_t)d * GG + cb * 32) * (2 * HH), 2 * HH, 0);
        load_hf(hsf, &g_h[0][0][0]);
        __syncthreads();
        gemm_ffma(hsf, wsf, acc);
        __syncthreads();
        load_Wf(wsf, w_ih1 + ((size_t)d * GG + cb * 32) * (2 * HH), 2 * HH, HH);
        load_hf(hsf, &g_h[1][0][0]);
        __syncthreads();
        gemm_ffma(hsf, wsf, acc);
        reduce_store_u((float*)(dynbuf + A_OFF), d, cb, acc);
    }
    bar_wait(dcnt, targ_d, 64);
    g1_finalize(d, cb, g1row, red, ln_ih1_g + d * GG, ln_ih1_b + d * GG);
    c = 0.f;
    __syncthreads();
    loadW_bf16(dynbuf, w_hh1 + ((size_t)d * GG + cb * 32) * HH);
    load_params(hhg, hhb, hog, hob, ln_hh1_g + d * GG, ln_hh1_b + d * GG,
                ln_ho1_g + d * HH, ln_ho1_b + d * HH);
    bar_wait(dcnt, targ_d, 64);

    // ---- layer 1 scan (per-direction) ----
    for (int st = 0; st < SS; st++) {
        step_gemm_mma(d, cb, dynbuf, base_u);
        bar_wait(dcnt, targ_d, 64);
        bool last = (st == SS - 1);
        step_point(d, cb, nullptr, g1row, 1, red, hhg, hhb, hog, hob, c,
                   last ? (out + (size_t)cb * 1024 + d * 512) : nullptr);
        if (!last) bar_wait(dcnt, targ_d, 64);
    }

    // ---- exit protocol: last CTA resets all barrier counters ----
    __syncthreads();
    if (t == 0) {
        __threadfence();
        unsigned n = atomicAdd(&g_excnt, 1u) + 1;
        if (n == NCTA) {
            g_bar_d[0][0] = 0;
            g_bar_d[1][0] = 0;
            g_bar_all = 0;
            g_excnt = 0;
            __threadfence();
        }
    }
}

// =============================================================================
extern "C" void kernel_launch(void* const* d_in, const int* in_sizes, int n_in,
                              void* d_out, int out_size) {
    const float* x        = (const float*)d_in[0];
    // d_in[1] = text_length (unused by the reference forward)
    const float* w_ih0    = (const float*)d_in[2];
    const float* w_hh0    = (const float*)d_in[3];
    const float* ln_ih0_g = (const float*)d_in[4];
    const float* ln_ih0_b = (const float*)d_in[5];
    const float* ln_hh0_g = (const float*)d_in[6];
    const float* ln_hh0_b = (const float*)d_in[7];
    const float* ln_ho0_g = (const float*)d_in[8];
    const float* ln_ho0_b = (const float*)d_in[9];
    const float* w_ih1    = (const float*)d_in[10];
    const float* w_hh1    = (const float*)d_in[11];
    const float* ln_ih1_g = (const float*)d_in[12];
    const float* ln_ih1_b = (const float*)d_in[13];
    const float* ln_hh1_g = (const float*)d_in[14];
    const float* ln_hh1_b = (const float*)d_in[15];
    const float* ln_ho1_g = (const float*)d_in[16];
    const float* ln_ho1_b = (const float*)d_in[17];
    float* out = (float*)d_out;

    static int smem_set = 0;
    if (!smem_set) {
        cudaFuncSetAttribute(scan_kernel, cudaFuncAttributeMaxDynamicSharedMemorySize,
                             SCAN_SMEM_BYTES);
        smem_set = 1;
    }

    phaseA_gemm<<<2 * SS * 32, 256>>>(x, w_ih0);
    phaseA_ln<<<2 * SS * BB, 256>>>(ln_ih0_g, ln_ih0_b);
    scan_kernel<<<NCTA, 512, SCAN_SMEM_BYTES>>>(
        w_hh0, ln_hh0_g, ln_hh0_b, ln_ho0_g, ln_ho0_b,
        w_ih1, w_hh1, ln_ih1_g, ln_ih1_b,
        ln_hh1_g, ln_hh1_b, ln_ho1_g, ln_ho1_b, out);
}

// round 16
// speedup vs baseline: 1.7169x; 1.1375x over previous
#include <cuda_runtime.h>
#include <cuda_fp16.h>
#include <cstdint>

#define BB 64
#define SS 48
#define EE 512
#define HH 512
#define GG 2048
#define NCTA 128

// ---------------- persistent device scratch (no allocs allowed) ----------------
__device__ float g_gih0[2][SS][BB][GG];   // LN(x @ W_ih0^T), both dirs  (~50MB)
__device__ float g_u[2][BB][GG];          // per-step h @ W_hh^T (raw)
__device__ float g_h[2][BB][HH];
__device__ __half g_hh[2][2][BB][HH];     // [dir][hi/lo] fp16 2-way split of h
__device__ unsigned g_bar_d[2][32];       // per-direction barrier counters (padded)
__device__ unsigned g_bar_all = 0;        // full-grid join barrier
__device__ unsigned g_excnt = 0;

// fast activations (verified R12/R15: no rel_err movement)
__device__ __forceinline__ float sigmoidf_(float x) {
    return __fdividef(1.0f, 1.0f + __expf(-x));
}
__device__ __forceinline__ float tanhf_(float x) {
    float xx = fminf(fmaxf(x, -15.f), 15.f);
    float e = __expf(2.f * xx);
    return __fdividef(e - 1.f, e + 1.f);
}

__device__ __forceinline__ uint32_t smem_u32(const void* p) {
    uint32_t a;
    asm("{ .reg .u64 t; cvta.to.shared.u64 t, %1; cvt.u32.u64 %0, t; }" : "=r"(a) : "l"(p));
    return a;
}

// ---------------- mma.sync helpers (baseline PTX; valid on sm_103) -------------
__device__ __forceinline__ void ldm_x4(uint32_t (&r)[4], uint32_t addr) {
    asm volatile("ldmatrix.sync.aligned.m8n8.x4.shared.b16 {%0,%1,%2,%3}, [%4];"
                 : "=r"(r[0]), "=r"(r[1]), "=r"(r[2]), "=r"(r[3]) : "r"(addr));
}
__device__ __forceinline__ void mma_f16(float (&c)[4], const uint32_t (&a)[4],
                                        uint32_t b0, uint32_t b1) {
    asm volatile(
        "mma.sync.aligned.m16n8k16.row.col.f32.f16.f16.f32 "
        "{%0,%1,%2,%3}, {%4,%5,%6,%7}, {%8,%9}, {%0,%1,%2,%3};"
        : "+f"(c[0]), "+f"(c[1]), "+f"(c[2]), "+f"(c[3])
        : "r"(a[0]), "r"(a[1]), "r"(a[2]), "r"(a[3]), "r"(b0), "r"(b1));
}

// ---------------- barriers -----------------------------------------------------
__device__ __forceinline__ void bar_wait(unsigned* cnt, unsigned &target, unsigned inc) {
    __syncthreads();
    if (threadIdx.x == 0) {
        __threadfence();                       // release this CTA's global stores
        atomicAdd(cnt, 1u);
        target += inc;
        while (*(volatile unsigned*)cnt < target) { __nanosleep(40); }
        __threadfence();                       // acquire: invalidate stale L1
    }
    __syncthreads();
}

// ---------------- block stats: static-shared version (phaseA kernels) ----------
template <int NW>
__device__ __forceinline__ void block_stats(float s, float q, float invN,
                                            float &mu, float &rs) {
    __shared__ float redS[NW], redQ[NW], bc[2];
    int t = threadIdx.x;
    __syncthreads();
#pragma unroll
    for (int o = 16; o > 0; o >>= 1) {
        s += __shfl_xor_sync(0xFFFFFFFFu, s, o);
        q += __shfl_xor_sync(0xFFFFFFFFu, q, o);
    }
    if ((t & 31) == 0) { redS[t >> 5] = s; redQ[t >> 5] = q; }
    __syncthreads();
    if (t == 0) {
        float S = 0.f, Q = 0.f;
#pragma unroll
        for (int i = 0; i < NW; i++) { S += redS[i]; Q += redQ[i]; }
        float m = S * invN;
        bc[0] = m;
        bc[1] = rsqrtf(Q * invN - m * m + 1e-5f);
    }
    __syncthreads();
    mu = bc[0]; rs = bc[1];
}

// dynamic-scratch version for the scan kernel (512 threads = 16 warps)
__device__ __forceinline__ void block_stats_d(float s, float q, float invN,
                                              float &mu, float &rs, float* red) {
    int t = threadIdx.x;
    __syncthreads();
#pragma unroll
    for (int o = 16; o > 0; o >>= 1) {
        s += __shfl_xor_sync(0xFFFFFFFFu, s, o);
        q += __shfl_xor_sync(0xFFFFFFFFu, q, o);
    }
    if ((t & 31) == 0) { red[t >> 5] = s; red[16 + (t >> 5)] = q; }
    __syncthreads();
    if (t == 0) {
        float S = 0.f, Q = 0.f;
#pragma unroll
        for (int i = 0; i < 16; i++) { S += red[i]; Q += red[16 + i]; }
        float m = S * invN;
        red[32] = m;
        red[33] = rsqrtf(Q * invN - m * m + 1e-5f);
    }
    __syncthreads();
    mu = red[32]; rs = red[33];
}

// ================= Phase A: raw x @ W_ih0^T (FFMA version; at chip floor) ======
__global__ void __launch_bounds__(256, 2) phaseA_gemm(const float* __restrict__ x,
                                                      const float* __restrict__ w_ih0) {
    __shared__ float xs[64][68];
    __shared__ float ws[64][68];
    int r = blockIdx.x;
    int d = r / (SS * 32);
    int rem = r % (SS * 32);
    int s = rem / 32;
    int g0 = (rem % 32) * 64;

    int t = threadIdx.x;
    int tb = t & 15;
    int tg = t >> 4;

    float acc[4][4];
#pragma unroll
    for (int i = 0; i < 4; i++)
#pragma unroll
        for (int j = 0; j < 4; j++) acc[i][j] = 0.f;

    for (int kt = 0; kt < EE / 64; kt++) {
        int k0 = kt * 64;
#pragma unroll
        for (int i = 0; i < 4; i++) {
            int fi = t + 256 * i;
            int b = fi >> 4, kq = fi & 15;
            *(float4*)&xs[b][kq * 4] =
                *(const float4*)(x + ((size_t)b * SS + s) * EE + k0 + kq * 4);
        }
#pragma unroll
        for (int i = 0; i < 4; i++) {
            int fi = t + 256 * i;
            int gg = fi >> 4, kq = fi & 15;
            *(float4*)&ws[gg][kq * 4] =
                *(const float4*)(w_ih0 + ((size_t)d * GG + g0 + gg) * EE + k0 + kq * 4);
        }
        __syncthreads();
#pragma unroll 4
        for (int k = 0; k < 64; k += 4) {
            float4 wv[4];
#pragma unroll
            for (int j = 0; j < 4; j++) wv[j] = *(float4*)&ws[tg + 16 * j][k];
#pragma unroll
            for (int i = 0; i < 4; i++) {
                float4 hv = *(float4*)&xs[tb + 16 * i][k];
#pragma unroll
                for (int j = 0; j < 4; j++) {
                    acc[i][j] += hv.x * wv[j].x + hv.y * wv[j].y
                               + hv.z * wv[j].z + hv.w * wv[j].w;
                }
            }
        }
        __syncthreads();
    }
#pragma unroll
    for (int i = 0; i < 4; i++) {
        int b = tb + 16 * i;
#pragma unroll
        for (int j = 0; j < 4; j++)
            g_gih0[d][s][b][g0 + tg + 16 * j] = acc[i][j];
    }
}

// ================= Phase A LN (unchanged) ======================================
__global__ void __launch_bounds__(256) phaseA_ln(const float* __restrict__ gam,
                                                 const float* __restrict__ bet) {
    int r = blockIdx.x;
    int d = r / (SS * BB);
    int rem = r % (SS * BB);
    int s = rem / BB;
    int b = rem % BB;
    float* row = &g_gih0[d][s][b][0];
    int t = threadIdx.x;
    float v[8];
    float sum = 0.f, sq = 0.f;
#pragma unroll
    for (int i = 0; i < 8; i++) {
        v[i] = row[t + 256 * i];
        sum += v[i]; sq += v[i] * v[i];
    }
    float mu, rs;
    block_stats<8>(sum, sq, 1.0f / GG, mu, rs);
    const float* gm = gam + d * GG;
    const float* bt = bet + d * GG;
#pragma unroll
    for (int i = 0; i < 8; i++) {
        int g = t + 256 * i;
        row[g] = (v[i] - mu) * rs * gm[g] + bt[g];
    }
}

// ================= scan-kernel smem layout (byte offsets into dynbuf) ==========
#define A_OFF 256
#define AREG_B 73728
#define W_OFF (A_OFF + AREG_B)
#define WSPL_B 33280
#define CW_OFF (A_OFF + 132096)
#define P_OFF 198400
#define SCAN_SMEM_BYTES (P_OFF + 28672)

// convert this CTA's 32 W rows (fp32, K=512) into fp16 hi/lo padded tiles
__device__ void loadW_f16(unsigned char* dyn, const float* __restrict__ Wg) {
    int t = threadIdx.x;
    __half* w0 = (__half*)(dyn + W_OFF);
    __half* w1 = (__half*)(dyn + W_OFF + WSPL_B);
#pragma unroll
    for (int i = 0; i < 32; i++) {
        int idx = t + 512 * i;            // g = idx>>9, k = idx&511
        int g = idx >> 9, k = idx & 511;
        float v = Wg[(size_t)g * HH + k];
        __half hi = __float2half_rn(v);
        float lof = v - __half2float(hi);
        w0[g * 520 + k] = hi;
        w1[g * 520 + k] = __float2half_rn(lof);
    }
}

// ================= tensor-core step GEMM (mma.sync, 3-term fp16 2-way split) ===
// u[d][b=0..63][cb*32..+32) = h[64][512] @ W[32][512]^T
// pass 0: A = h_hi, B = {W_hi, W_lo};  pass 1: A = h_lo, B = {W_hi}
__device__ void step_gemm_mma(int d, int cb, unsigned char* dyn, uint32_t base_u) {
    int t = threadIdx.x;
    int lane = t & 31, w = t >> 5;
    int mh = w >> 3, ks = w & 7;
    int q = lane >> 3, rr = lane & 7;
    int gid = lane >> 2, tid2 = lane & 3;
    uint32_t hs_u = base_u + A_OFF;
    uint32_t ws_u = base_u + W_OFF;

    float c[2][4][4];
#pragma unroll
    for (int mi = 0; mi < 2; mi++)
#pragma unroll
        for (int nj = 0; nj < 4; nj++)
#pragma unroll
            for (int e = 0; e < 4; e++) c[mi][nj][e] = 0.f;

    int arow = mh * 32 + (q & 1) * 8 + rr;
    int acol = (q >> 1) * 8;
    int brow = (q >> 1) * 8 + rr;
    int bcol = (q & 1) * 8;

#pragma unroll
    for (int p = 0; p < 2; p++) {
        __syncthreads();                      // prior pass reads done before overwrite
        {   // fill h split p: 64 rows x 512 fp16 = 4096 float4
            const float4* src = (const float4*)&g_hh[d][p][0][0];
            __half* hdst = (__half*)(dyn + A_OFF);
#pragma unroll
            for (int i = 0; i < 8; i++) {
                int idx = t + 512 * i;
                int row = idx >> 6, cc = idx & 63;
                *(float4*)(hdst + row * 520 + cc * 8) = src[idx];
            }
        }
        __syncthreads();
        const int nB = 2 - p;
#pragma unroll
        for (int kk = 0; kk < 4; kk++) {
            int k = ks * 64 + kk * 16;
            uint32_t a[2][4];
#pragma unroll
            for (int mi = 0; mi < 2; mi++)
                ldm_x4(a[mi], hs_u + (uint32_t)(((arow + mi * 16) * 520 + k + acol) * 2));
#pragma unroll
            for (int wb = 0; wb < 2; wb++) {
                if (wb >= nB) break;
                uint32_t Bb = ws_u + (uint32_t)wb * WSPL_B;
                uint32_t bf[2][4];
#pragma unroll
                for (int njp = 0; njp < 2; njp++)
                    ldm_x4(bf[njp], Bb + (uint32_t)(((brow + njp * 16) * 520 + k + bcol) * 2));
#pragma unroll
                for (int mi = 0; mi < 2; mi++) {
                    mma_f16(c[mi][0], a[mi], bf[0][0], bf[0][1]);
                    mma_f16(c[mi][1], a[mi], bf[0][2], bf[0][3]);
                    mma_f16(c[mi][2], a[mi], bf[1][0], bf[1][1]);
                    mma_f16(c[mi][3], a[mi], bf[1][2], bf[1][3]);
                }
            }
        }
    }
    __syncthreads();                          // A tile dead; region becomes scratch

    float* scr = (float*)(dyn + A_OFF);
#pragma unroll
    for (int mi = 0; mi < 2; mi++)
#pragma unroll
        for (int nj = 0; nj < 4; nj++) {
            int b = mh * 32 + mi * 16 + gid;
            int n = nj * 8 + tid2 * 2;
            scr[ks * 2304 + b * 36 + n]           = c[mi][nj][0];
            scr[ks * 2304 + b * 36 + n + 1]       = c[mi][nj][1];
            scr[ks * 2304 + (b + 8) * 36 + n]     = c[mi][nj][2];
            scr[ks * 2304 + (b + 8) * 36 + n + 1] = c[mi][nj][3];
        }
    __syncthreads();
#pragma unroll
    for (int i = 0; i < 4; i++) {
        int e = t + 512 * i;
        int b = e >> 5, n = e & 31;
        float s = 0.f;
#pragma unroll
        for (int p = 0; p < 8; p++) s += scr[p * 2304 + b * 36 + n];
        g_u[d][b][cb * 32 + n] = s;
    }
}

// ---------------- fp32 FFMA path for the one-time concat GEMM -----------------
__device__ __forceinline__ void load_Wf(float (*ws)[516], const float* __restrict__ Wbase,
                                        int rowStride, int colOff) {
    int t = threadIdx.x;
#pragma unroll
    for (int i = 0; i < 8; i++) {
        int fi = t + 512 * i;
        int g = fi >> 7, kq = fi & 127;
        *(float4*)&ws[g][kq * 4] =
            *(const float4*)(Wbase + (size_t)g * rowStride + colOff + kq * 4);
    }
}
__device__ __forceinline__ void load_hf(float (*hs)[516], const float* __restrict__ src) {
    int t = threadIdx.x;
#pragma unroll
    for (int i = 0; i < 16; i++) {
        int fi = t + 512 * i;
        int b = fi >> 7, kq = fi & 127;
        *(float4*)&hs[b][kq * 4] = *(const float4*)(src + (size_t)b * HH + kq * 4);
    }
}
__device__ __forceinline__ void gemm_ffma(float (*hs)[516], float (*ws)[516],
                                          float (&acc)[4][2]) {
    int t = threadIdx.x;
    int half = t >> 8;
    int tl = t & 255;
    int tb = tl & 15;
    int tg = tl >> 4;
    const int kk0 = half << 8;
#pragma unroll 4
    for (int k = 0; k < 256; k += 8) {
        float4 w0a = *(const float4*)&ws[2 * tg][kk0 + k];
        float4 w1a = *(const float4*)&ws[2 * tg + 1][kk0 + k];
        float4 w0b = *(const float4*)&ws[2 * tg][kk0 + k + 4];
        float4 w1b = *(const float4*)&ws[2 * tg + 1][kk0 + k + 4];
        float4 ha[4], hb[4];
#pragma unroll
        for (int i = 0; i < 4; i++) {
            ha[i] = *(const float4*)&hs[tb + 16 * i][kk0 + k];
            hb[i] = *(const float4*)&hs[tb + 16 * i][kk0 + k + 4];
        }
#pragma unroll
        for (int i = 0; i < 4; i++) {
            acc[i][0] += ha[i].x * w0a.x + ha[i].y * w0a.y + ha[i].z * w0a.z + ha[i].w * w0a.w;
            acc[i][1] += ha[i].x * w1a.x + ha[i].y * w1a.y + ha[i].z * w1a.z + ha[i].w * w1a.w;
        }
#pragma unroll
        for (int i = 0; i < 4; i++) {
            acc[i][0] += hb[i].x * w0b.x + hb[i].y * w0b.y + hb[i].z * w0b.z + hb[i].w * w0b.w;
            acc[i][1] += hb[i].x * w1b.x + hb[i].y * w1b.y + hb[i].z * w1b.z + hb[i].w * w1b.w;
        }
    }
}
__device__ __forceinline__ void reduce_store_u(float* scratch, int d, int chunk,
                                               float (&acc)[4][2]) {
    int t = threadIdx.x;
    int half = t >> 8;
    int tl = t & 255;
    int tb = tl & 15, tg = tl >> 4;
    __syncthreads();
    if (half == 1) {
#pragma unroll
        for (int i = 0; i < 4; i++) {
            int b = tb + 16 * i;
            scratch[(2 * tg) * 64 + b]     = acc[i][0];
            scratch[(2 * tg + 1) * 64 + b] = acc[i][1];
        }
    }
    __syncthreads();
    if (half == 0) {
#pragma unroll
        for (int i = 0; i < 4; i++) {
            int b = tb + 16 * i;
            float2 o;
            o.x = acc[i][0] + scratch[(2 * tg) * 64 + b];
            o.y = acc[i][1] + scratch[(2 * tg + 1) * 64 + b];
            *(float2*)&g_u[d][b][chunk * 32 + 2 * tg] = o;
        }
    }
}

// ================= pointwise: CTA owns row (d, b); 1 hidden unit per thread ====
__device__ void step_point(int d, int b, const float* gihr, const float* g1row,
                           int useG1, float* red, const float* hhg, const float* hhb,
                           const float* hog, const float* hob, float &c,
                           float* __restrict__ outrow) {
    int j = threadIdx.x;
    const float* urow = &g_u[d][b][0];
    float uv[4], gv4[4];
    float s = 0.f, q = 0.f;
#pragma unroll
    for (int m = 0; m < 4; m++) {
        uv[m] = urow[j + 512 * m];
        s += uv[m]; q += uv[m] * uv[m];
        gv4[m] = useG1 ? g1row[j + 512 * m] : gihr[m];
    }
    float mu, rs;
    block_stats_d(s, q, 1.0f / GG, mu, rs, red);

    float vi = gv4[0] + (uv[0] - mu) * rs * hhg[j]        + hhb[j];
    float vf = gv4[1] + (uv[1] - mu) * rs * hhg[512 + j]  + hhb[512 + j];
    float vo = gv4[2] + (uv[2] - mu) * rs * hhg[1024 + j] + hhb[1024 + j];
    float vg = gv4[3] + (uv[3] - mu) * rs * hhg[1536 + j] + hhb[1536 + j];
    float ig = sigmoidf_(vi);
    float fg = sigmoidf_(vf);
    float og = sigmoidf_(vo);
    float gg = tanhf_(vg);
    float cn = fg * c + ig * gg;

    float muc, rsc;
    block_stats_d(cn, cn * cn, 1.0f / HH, muc, rsc, red);
    float hval = og * tanhf_((cn - muc) * rsc * hog[j] + hob[j]);
    c = cn;
    g_h[d][b][j] = hval;
    // fp16 2-way split for next step's tensor GEMM
    __half hi = __float2half_rn(hval);
    float lof = hval - __half2float(hi);
    g_hh[d][0][b][j] = hi;
    g_hh[d][1][b][j] = __float2half_rn(lof);
    if (outrow) outrow[j] = hval;
}

// layer-1 input LN into smem g1row; reset h (fp32 + fp16) for layer 1
__device__ void g1_finalize(int d, int b, float* g1row, float* red,
                            const float* __restrict__ ihg, const float* __restrict__ ihb) {
    int t = threadIdx.x;
    const float* urow = &g_u[d][b][0];
    float uv[4];
    float s = 0.f, q = 0.f;
#pragma unroll
    for (int m = 0; m < 4; m++) {
        uv[m] = urow[t + 512 * m];
        s += uv[m]; q += uv[m] * uv[m];
    }
    float mu, rs;
    block_stats_d(s, q, 1.0f / GG, mu, rs, red);
#pragma unroll
    for (int m = 0; m < 4; m++) {
        int g = t + 512 * m;
        g1row[g] = (uv[m] - mu) * rs * ihg[g] + ihb[g];
    }
    g_h[d][b][t] = 0.f;
    g_hh[d][0][b][t] = __float2half_rn(0.f);
    g_hh[d][1][b][t] = __float2half_rn(0.f);
}

__device__ void load_params(float* hhg, float* hhb, float* hog, float* hob,
                            const float* shhg, const float* shhb,
                            const float* shog, const float* shob) {
    int t = threadIdx.x;
#pragma unroll
    for (int i = 0; i < 4; i++) {
        int j = t + 512 * i;
        hhg[j] = shhg[j];
        hhb[j] = shhb[j];
    }
    hog[t] = shog[t];
    hob[t] = shob[t];
}

// ================= persistent recurrent kernel ================================
__global__ void __launch_bounds__(512, 1) scan_kernel(
    const float* __restrict__ w_hh0,
    const float* __restrict__ ln_hh0_g, const float* __restrict__ ln_hh0_b,
    const float* __restrict__ ln_ho0_g, const float* __restrict__ ln_ho0_b,
    const float* __restrict__ w_ih1, const float* __restrict__ w_hh1,
    const float* __restrict__ ln_ih1_g, const float* __restrict__ ln_ih1_b,
    const float* __restrict__ ln_hh1_g, const float* __restrict__ ln_hh1_b,
    const float* __restrict__ ln_ho1_g, const float* __restrict__ ln_ho1_b,
    float* __restrict__ out) {
    extern __shared__ unsigned char dynbuf[];
    uint32_t base_u = smem_u32(dynbuf);
    float* red = (float*)dynbuf;
    float* P = (float*)(dynbuf + P_OFF);
    float* hhg = P;
    float* hhb = P + 2048;
    float* hog = P + 4096;
    float* hob = P + 4608;
    float* g1row = P + 5120;

    int r = blockIdx.x;
    int d = r >> 6;
    int cb = r & 63;
    int t = threadIdx.x;
    unsigned targ_d = 0;       // per-direction barrier target
    unsigned targ_all = 0;     // full-grid barrier target
    unsigned* dcnt = &g_bar_d[d][0];
    float c = 0.f;

    // one-time setup
    loadW_f16(dynbuf, w_hh0 + ((size_t)d * GG + cb * 32) * HH);
    load_params(hhg, hhb, hog, hob, ln_hh0_g + d * GG, ln_hh0_b + d * GG,
                ln_ho0_g + d * HH, ln_ho0_b + d * HH);
    g_h[d][cb][t] = 0.f;
    g_hh[d][0][cb][t] = __float2half_rn(0.f);
    g_hh[d][1][cb][t] = __float2half_rn(0.f);
    bar_wait(dcnt, targ_d, 64);

    // ---- layer 0 scan (per-direction barriers; dirs fully independent) ----
    for (int st = 0; st < SS; st++) {
        int te = (d == 0) ? st : (SS - 1 - st);
        const float* gptr = &g_gih0[d][te][cb][0];
        float gihr[4];
#pragma unroll
        for (int m = 0; m < 4; m++) gihr[m] = gptr[t + 512 * m];
        step_gemm_mma(d, cb, dynbuf, base_u);
        bar_wait(dcnt, targ_d, 64);
        step_point(d, cb, gihr, g1row, 0, red, hhg, hhb, hog, hob, c, nullptr);
        bar_wait(dcnt, targ_d, 64);
    }

    // ---- join: concat GEMM reads BOTH directions' h ----
    bar_wait(&g_bar_all, targ_all, 128);
    {
        float (*hsf)[516] = (float (*)[516])(dynbuf + A_OFF);
        float (*wsf)[516] = (float (*)[516])(dynbuf + CW_OFF);
        float acc[4][2];
#pragma unroll
        for (int i = 0; i < 4; i++) { acc[i][0] = 0.f; acc[i][1] = 0.f; }
        load_Wf(wsf, w_ih1 + ((size_t)d * GG + cb * 32) * (2 * HH), 2 * HH, 0);
        load_hf(hsf, &g_h[0][0][0]);
        __syncthreads();
        gemm_ffma(hsf, wsf, acc);
        __syncthreads();
        load_Wf(wsf, w_ih1 + ((size_t)d * GG + cb * 32) * (2 * HH), 2 * HH, HH);
        load_hf(hsf, &g_h[1][0][0]);
        __syncthreads();
        gemm_ffma(hsf, wsf, acc);
        reduce_store_u((float*)(dynbuf + A_OFF), d, cb, acc);
    }
    bar_wait(dcnt, targ_d, 64);
    g1_finalize(d, cb, g1row, red, ln_ih1_g + d * GG, ln_ih1_b + d * GG);
    c = 0.f;
    __syncthreads();
    loadW_f16(dynbuf, w_hh1 + ((size_t)d * GG + cb * 32) * HH);
    load_params(hhg, hhb, hog, hob, ln_hh1_g + d * GG, ln_hh1_b + d * GG,
                ln_ho1_g + d * HH, ln_ho1_b + d * HH);
    bar_wait(dcnt, targ_d, 64);

    // ---- layer 1 scan (per-direction) ----
    for (int st = 0; st < SS; st++) {
        step_gemm_mma(d, cb, dynbuf, base_u);
        bar_wait(dcnt, targ_d, 64);
        bool last = (st == SS - 1);
        step_point(d, cb, nullptr, g1row, 1, red, hhg, hhb, hog, hob, c,
                   last ? (out + (size_t)cb * 1024 + d * 512) : nullptr);
        if (!last) bar_wait(dcnt, targ_d, 64);
    }

    // ---- exit protocol: last CTA resets all barrier counters ----
    __syncthreads();
    if (t == 0) {
        __threadfence();
        unsigned n = atomicAdd(&g_excnt, 1u) + 1;
        if (n == NCTA) {
            g_bar_d[0][0] = 0;
            g_bar_d[1][0] = 0;
            g_bar_all = 0;
            g_excnt = 0;
            __threadfence();
        }
    }
}

// =============================================================================
extern "C" void kernel_launch(void* const* d_in, const int* in_sizes, int n_in,
                              void* d_out, int out_size) {
    const float* x        = (const float*)d_in[0];
    // d_in[1] = text_length (unused by the reference forward)
    const float* w_ih0    = (const float*)d_in[2];
    const float* w_hh0    = (const float*)d_in[3];
    const float* ln_ih0_g = (const float*)d_in[4];
    const float* ln_ih0_b = (const float*)d_in[5];
    const float* ln_hh0_g = (const float*)d_in[6];
    const float* ln_hh0_b = (const float*)d_in[7];
    const float* ln_ho0_g = (const float*)d_in[8];
    const float* ln_ho0_b = (const float*)d_in[9];
    const float* w_ih1    = (const float*)d_in[10];
    const float* w_hh1    = (const float*)d_in[11];
    const float* ln_ih1_g = (const float*)d_in[12];
    const float* ln_ih1_b = (const float*)d_in[13];
    const float* ln_hh1_g = (const float*)d_in[14];
    const float* ln_hh1_b = (const float*)d_in[15];
    const float* ln_ho1_g = (const float*)d_in[16];
    const float* ln_ho1_b = (const float*)d_in[17];
    float* out = (float*)d_out;

    static int smem_set = 0;
    if (!smem_set) {
        cudaFuncSetAttribute(scan_kernel, cudaFuncAttributeMaxDynamicSharedMemorySize,
                             SCAN_SMEM_BYTES);
        smem_set = 1;
    }

    phaseA_gemm<<<2 * SS * 32, 256>>>(x, w_ih0);
    phaseA_ln<<<2 * SS * BB, 256>>>(ln_ih0_g, ln_ih0_b);
    scan_kernel<<<NCTA, 512, SCAN_SMEM_BYTES>>>(
        w_hh0, ln_hh0_g, ln_hh0_b, ln_ho0_g, ln_ho0_b,
        w_ih1, w_hh1, ln_ih1_g, ln_ih1_b,
        ln_hh1_g, ln_hh1_b, ln_ho1_g, ln_ho1_b, out);
}